// round 6
// baseline (speedup 1.0000x reference)
#include <cuda_runtime.h>
#include <cuda_bf16.h>

#define NBATCH 32
#define NSUP   100   // n_support
#define NWAY   10    // n_way
#define NZV    1000  // nz = NSUP*NWAY
#define NQRY   150   // N*Q queries

// ---------------- device scratch (no runtime allocation allowed) ----------------
__device__ float g_krn   [NBATCH * NSUP * NSUP];          // sup sup^T        (100x100)
__device__ float g_compat[NBATCH * NSUP * NQRY];          // sup qry^T        (100x150)
__device__ float g_Hinv  [NBATCH * NWAY * NSUP * NSUP];   // per-class H_c^{-1}
__device__ float g_t     [NBATCH * NWAY * NSUP];          // t_c = Hinv_c r1_c
__device__ float g_z  [NBATCH * NZV];
__device__ float g_s  [NBATCH * NZV];
__device__ float g_lam[NBATCH * NZV];
__device__ float g_nu [NBATCH * NSUP];
__device__ float g_rp [NBATCH * NZV];
__device__ float g_rc [NBATCH * NZV];
__device__ float g_r1 [NBATCH * NZV];
__device__ float g_d  [NBATCH * NZV];
__device__ float g_rp2[NBATCH * NSUP];

// ---------------- block reductions (blockDim.x == 256) ----------------
__device__ __forceinline__ float blk_reduce_sum(float v, float* red, int tid) {
    red[tid] = v;
    __syncthreads();
#pragma unroll
    for (int s = 128; s > 0; s >>= 1) {
        if (tid < s) red[tid] += red[tid + s];
        __syncthreads();
    }
    float r = red[0];
    __syncthreads();
    return r;
}

__device__ __forceinline__ float blk_reduce_min(float v, float* red, int tid) {
    red[tid] = v;
    __syncthreads();
#pragma unroll
    for (int s = 128; s > 0; s >>= 1) {
        if (tid < s) red[tid] = fminf(red[tid], red[tid + s]);
        __syncthreads();
    }
    float r = red[0];
    __syncthreads();
    return r;
}

// ---------------- residuals (shared by k_init and k_schur tail) ----------------
// Computes rp2, mu, and per-entry rp, rc, d, r1 from current (z, nu, s, lam).
// sh_z must hold the full z for this batch (synced); nu_sh the full nu.
// g_s/g_lam are read with the SAME i = tid + k*256 mapping their writers used,
// so same-thread program order guarantees visibility without extra fences.
__device__ void compute_resid(int b, int tid, const int* __restrict__ lab,
                              const float* __restrict__ sh_z,
                              const float* __restrict__ nu_sh,
                              float* red) {
    // rp2[s] = sum_c z[s,c]   (b = 0 for A z since b-vector is zero)
    for (int ss = tid; ss < NSUP; ss += 256) {
        float acc = 0.f;
#pragma unroll
        for (int c = 0; c < NWAY; c++) acc += sh_z[ss * NWAY + c];
        g_rp2[b * NSUP + ss] = acc;
    }
    // mu = dot(s, lam) / nineq
    float loc = 0.f;
    for (int i = tid; i < NZV; i += 256)
        loc += g_s[b * NZV + i] * g_lam[b * NZV + i];
    float mu = blk_reduce_sum(loc, red, tid) * (1.0f / (float)NZV);

    // per-entry residuals; kz = (kernel Z)[s,c]
    for (int i = tid; i < NZV; i += 256) {
        int ss = i / NWAY, c = i - ss * NWAY;
        const float* krow = &g_krn[b * NSUP * NSUP + ss * NSUP];
        float kz = 0.f;
        for (int j = 0; j < NSUP; j++)
            kz = fmaf(krow[j], sh_z[j * NWAY + c], kz);
        int gi = b * NZV + i;
        float y  = (lab[b * NSUP + ss] == c) ? 1.f : 0.f;
        float zi = sh_z[i];
        float sv = g_s[gi], lv = g_lam[gi];
        float rd = kz + zi - y + lv + nu_sh[ss];   // G z + e + lam + A^T nu
        float rp = zi + sv - 0.1f * y;             // z + s - h   (h = C*y, C=0.1)
        float rc = lv * sv - 0.1f * mu;
        float invs = 1.0f / sv;
        g_rp[gi] = rp;
        g_rc[gi] = rc;
        g_d [gi] = lv * invs;
        g_r1[gi] = -rd + (rc - lv * rp) * invs;
    }
}

// ---------------- gram: kernel (100x100) + compat (100x150) ----------------
// grid (32, 4), block 400. Output columns: 0..99 -> kernel, 100..249 -> compat.
__global__ void __launch_bounds__(400) k_gram(const float* __restrict__ sup,
                                              const float* __restrict__ qry) {
    int b  = blockIdx.x;
    int c0 = blockIdx.y * 64;
    __shared__ __align__(16) float As[32 * 100];  // [kk][row], stride 100 (16B aligned rows)
    __shared__ __align__(16) float Bs[32 * 64];   // [kk][col], stride 64
    int tid = threadIdx.x;
    int tx = tid & 15;        // 16 col groups of 4
    int ty = tid >> 4;        // 25 row groups of 4
    float acc[4][4];
#pragma unroll
    for (int u = 0; u < 4; u++)
#pragma unroll
        for (int v = 0; v < 4; v++) acc[u][v] = 0.f;

    const float* supb = sup + (size_t)b * NSUP * 512;
    const float* qryb = qry + (size_t)b * NQRY * 512;

    for (int kt = 0; kt < 512; kt += 32) {
        __syncthreads();
        for (int e = tid; e < NSUP * 32; e += 400) {
            int r = e >> 5, kk = e & 31;
            As[kk * 100 + r] = supb[r * 512 + kt + kk];
        }
        for (int e = tid; e < 64 * 32; e += 400) {
            int cc = e >> 5, kk = e & 31;
            int col = c0 + cc;
            float v = 0.f;
            if (col < NSUP)      v = supb[col * 512 + kt + kk];
            else if (col < 250)  v = qryb[(col - NSUP) * 512 + kt + kk];
            Bs[kk * 64 + cc] = v;
        }
        __syncthreads();
#pragma unroll
        for (int kk = 0; kk < 32; kk++) {
            float4 a  = *(const float4*)(As + kk * 100 + 4 * ty);
            float4 bb = *(const float4*)(Bs + kk * 64 + 4 * tx);
            acc[0][0] = fmaf(a.x, bb.x, acc[0][0]); acc[0][1] = fmaf(a.x, bb.y, acc[0][1]);
            acc[0][2] = fmaf(a.x, bb.z, acc[0][2]); acc[0][3] = fmaf(a.x, bb.w, acc[0][3]);
            acc[1][0] = fmaf(a.y, bb.x, acc[1][0]); acc[1][1] = fmaf(a.y, bb.y, acc[1][1]);
            acc[1][2] = fmaf(a.y, bb.z, acc[1][2]); acc[1][3] = fmaf(a.y, bb.w, acc[1][3]);
            acc[2][0] = fmaf(a.z, bb.x, acc[2][0]); acc[2][1] = fmaf(a.z, bb.y, acc[2][1]);
            acc[2][2] = fmaf(a.z, bb.z, acc[2][2]); acc[2][3] = fmaf(a.z, bb.w, acc[2][3]);
            acc[3][0] = fmaf(a.w, bb.x, acc[3][0]); acc[3][1] = fmaf(a.w, bb.y, acc[3][1]);
            acc[3][2] = fmaf(a.w, bb.z, acc[3][2]); acc[3][3] = fmaf(a.w, bb.w, acc[3][3]);
        }
    }
#pragma unroll
    for (int u = 0; u < 4; u++) {
        int r = 4 * ty + u;
#pragma unroll
        for (int v = 0; v < 4; v++) {
            int col = c0 + 4 * tx + v;
            if (col < NSUP)
                g_krn[b * NSUP * NSUP + r * NSUP + col] = acc[u][v];
            else if (col < 250)
                g_compat[b * NSUP * NQRY + r * NQRY + (col - NSUP)] = acc[u][v];
        }
    }
}

// ---------------- init: state = (0, 0, 1, 1) + first residuals ----------------
__global__ void __launch_bounds__(256) k_init(const int* __restrict__ lab) {
    int b = blockIdx.x, tid = threadIdx.x;
    __shared__ float sh_z[NZV];
    __shared__ float nu_sh[NSUP];
    __shared__ float red[256];
    for (int i = tid; i < NZV; i += 256) {
        sh_z[i] = 0.f;
        g_z  [b * NZV + i] = 0.f;
        g_s  [b * NZV + i] = 1.f;
        g_lam[b * NZV + i] = 1.f;
    }
    for (int ss = tid; ss < NSUP; ss += 256) {
        nu_sh[ss] = 0.f;
        g_nu[b * NSUP + ss] = 0.f;
    }
    __syncthreads();
    compute_resid(b, tid, lab, sh_z, nu_sh, red);
}

// ---------------- per-class inversion: Hinv_c and t_c = Hinv_c r1_c ----------------
// grid = 320 (b*10 + c), block = 128. In-place Gauss-Jordan (SPD, no pivoting).
// Row stride 100 floats: rows are 16B aligned AND float4 granules are bank-group
// conflict-free (100/4 = 25 is odd -> (25*i + jb) mod 8 distinct).
__global__ void __launch_bounds__(128) k_invert() {
    int bc = blockIdx.x;
    int b = bc / NWAY, c = bc - b * NWAY;
    int tid = threadIdx.x;
    __shared__ __align__(16) float sA[NSUP * NSUP];
    __shared__ __align__(16) float s_row[NSUP];
    __shared__ float s_r1[NSUP];

    for (int e = tid; e < NSUP * NSUP; e += 128) {
        int i = e / NSUP, j = e - i * NSUP;
        float v = g_krn[b * NSUP * NSUP + e];
        if (i == j) v += 1.0f + g_d[b * NZV + i * NWAY + c];
        sA[e] = v;
    }
    if (tid < NSUP) s_r1[tid] = g_r1[b * NZV + tid * NWAY + c];
    __syncthreads();

    for (int k = 0; k < NSUP; k++) {
        float invp = 1.0f / sA[k * NSUP + k];
        // scaled pivot row (col k slot holds invp -> in-place inverse convention)
        for (int j = tid; j < NSUP; j += 128)
            s_row[j] = (j == k) ? invp : sA[k * NSUP + j] * invp;
        __syncthreads();
        if (tid < NSUP) {
            if (tid == k) {
                float4* dst = (float4*)(sA + k * NSUP);
                const float4* src = (const float4*)s_row;
#pragma unroll
                for (int jb = 0; jb < 25; jb++) dst[jb] = src[jb];
            } else {
                float f = sA[tid * NSUP + k];
                float4* Ar = (float4*)(sA + tid * NSUP);
                const float4* Rr = (const float4*)s_row;
#pragma unroll
                for (int jb = 0; jb < 25; jb++) {
                    float4 a = Ar[jb];
                    float4 rr = Rr[jb];
                    a.x = fmaf(-f, rr.x, a.x);
                    a.y = fmaf(-f, rr.y, a.y);
                    a.z = fmaf(-f, rr.z, a.z);
                    a.w = fmaf(-f, rr.w, a.w);
                    Ar[jb] = a;
                }
                sA[tid * NSUP + k] = -f * invp;   // column-k fixup
            }
        }
        __syncthreads();
    }

    for (int e = tid; e < NSUP * NSUP; e += 128)
        g_Hinv[(size_t)bc * (NSUP * NSUP) + e] = sA[e];
    if (tid < NSUP) {
        float acc = 0.f;
        for (int j = 0; j < NSUP; j++)
            acc = fmaf(sA[tid * NSUP + j], s_r1[j], acc);
        g_t[bc * NSUP + tid] = acc;
    }
}

// ---------------- Schur solve + step + next residuals ----------------
// grid = 32, block = 256.
__global__ void __launch_bounds__(256) k_schur(const int* __restrict__ lab) {
    int b = blockIdx.x, tid = threadIdx.x;
    __shared__ float S[NSUP * 101];   // stride 101: conflict-free lane-per-row scalar access
    __shared__ float rhs[NSUP];
    __shared__ float nu_sh[NSUP];
    __shared__ float sh_z[NZV];
    __shared__ float red[256];

    // S = sum_c Hinv_c ; rhs = sum_c t_c + rp2
    for (int e = tid; e < NSUP * NSUP; e += 256) {
        float acc = 0.f;
#pragma unroll
        for (int c = 0; c < NWAY; c++)
            acc += g_Hinv[(size_t)(b * NWAY + c) * (NSUP * NSUP) + e];
        S[(e / NSUP) * 101 + (e - (e / NSUP) * NSUP)] = acc;
    }
    for (int ss = tid; ss < NSUP; ss += 256) {
        float acc = g_rp2[b * NSUP + ss];
#pragma unroll
        for (int c = 0; c < NWAY; c++) acc += g_t[(b * NWAY + c) * NSUP + ss];
        rhs[ss] = acc;
        nu_sh[ss] = g_nu[b * NSUP + ss];
    }
    __syncthreads();

    // Gauss-Jordan solve S x = rhs (trailing columns only; x lands in rhs)
    for (int k = 0; k < NSUP; k++) {
        float invp = 1.0f / S[k * 101 + k];
        for (int j = k + 1 + tid; j < NSUP; j += 256) S[k * 101 + j] *= invp;
        if (tid == 0) rhs[k] *= invp;
        __syncthreads();
        if (tid < NSUP && tid != k) {
            float f = S[tid * 101 + k];
            for (int j = k + 1; j < NSUP; j++)
                S[tid * 101 + j] = fmaf(-f, S[k * 101 + j], S[tid * 101 + j]);
            rhs[tid] = fmaf(-f, rhs[k], rhs[tid]);
        }
        __syncthreads();
    }
    // rhs == dnu now

    // dz_c = t_c - Hinv_c dnu ; ds ; dlam ; alpha candidates
    const float FINF = __int_as_float(0x7f800000);
    float dzv[4], dsv[4], dlv[4];
    float amin = FINF;
#pragma unroll
    for (int r = 0; r < 4; r++) {
        int i = tid + r * 256;
        if (i < NZV) {
            int ss = i / NWAY, c = i - ss * NWAY;
            const float* Hrow = &g_Hinv[(size_t)(b * NWAY + c) * (NSUP * NSUP) + ss * NSUP];
            float acc = 0.f;
            for (int j = 0; j < NSUP; j++) acc = fmaf(Hrow[j], rhs[j], acc);
            float dz = g_t[(b * NWAY + c) * NSUP + ss] - acc;
            int gi = b * NZV + i;
            float sv = g_s[gi], lv = g_lam[gi];
            float ds = -g_rp[gi] - dz;
            float dl = (-g_rc[gi] - lv * ds) / sv;
            dzv[r] = dz; dsv[r] = ds; dlv[r] = dl;
            if (ds < 0.f) amin = fminf(amin, -sv / ds);
            if (dl < 0.f) amin = fminf(amin, -lv / dl);
        }
    }
    float m = blk_reduce_min(amin, red, tid);
    float alpha = fminf(1.0f, 0.99f * m);

    // state update
#pragma unroll
    for (int r = 0; r < 4; r++) {
        int i = tid + r * 256;
        if (i < NZV) {
            int gi = b * NZV + i;
            float zn = g_z[gi] + alpha * dzv[r];
            g_z[gi] = zn;
            sh_z[i] = zn;
            g_s[gi]   += alpha * dsv[r];
            g_lam[gi] += alpha * dlv[r];
        }
    }
    for (int ss = tid; ss < NSUP; ss += 256) {
        float nn = nu_sh[ss] + alpha * rhs[ss];
        nu_sh[ss] = nn;
        g_nu[b * NSUP + ss] = nn;
    }
    __syncthreads();

    // residuals for the next iteration (wasted on the last iter; harmless)
    compute_resid(b, tid, lab, sh_z, nu_sh, red);
}

// ---------------- logits epilogue ----------------
__global__ void __launch_bounds__(256) k_logits(float* __restrict__ out) {
    int b = blockIdx.x, tid = threadIdx.x;
    __shared__ float sh_z[NZV];
    for (int i = tid; i < NZV; i += 256) sh_z[i] = g_z[b * NZV + i];
    __syncthreads();
    const float* cb = &g_compat[b * NSUP * NQRY];
    for (int o = tid; o < NQRY * NWAY; o += 256) {
        int q = o / NWAY, n = o - q * NWAY;
        float acc = 0.f;
        for (int s = 0; s < NSUP; s++)
            acc = fmaf(cb[s * NQRY + q], sh_z[s * NWAY + n], acc);
        out[b * NQRY * NWAY + o] = acc;
    }
}

// ---------------- launcher ----------------
extern "C" void kernel_launch(void* const* d_in, const int* in_sizes, int n_in,
                              void* d_out, int out_size) {
    const float* sup = (const float*)d_in[0];   // (32,10,10,512)
    const int*   lab = (const int*)  d_in[1];   // (32,10,10)
    const float* qry = (const float*)d_in[2];   // (32,10,15,512)
    float* out = (float*)d_out;                 // (32,150,10)

    k_gram<<<dim3(NBATCH, 4), 400>>>(sup, qry);
    k_init<<<NBATCH, 256>>>(lab);
    for (int it = 0; it < 15; ++it) {
        k_invert<<<NBATCH * NWAY, 128>>>();
        k_schur<<<NBATCH, 256>>>(lab);
    }
    k_logits<<<NBATCH, 256>>>(out);
}

// round 7
// speedup vs baseline: 1.1201x; 1.1201x over previous
#include <cuda_runtime.h>
#include <cuda_bf16.h>

#define NBATCH 32
#define NSUP   100   // n_support
#define NWAY   10    // n_way
#define NZV    1000  // nz = NSUP*NWAY
#define NQRY   150   // N*Q queries

// ---------------- device scratch (no runtime allocation allowed) ----------------
__device__ float g_krn   [NBATCH * NSUP * NSUP];          // sup sup^T        (100x100)
__device__ float g_compat[NBATCH * NSUP * NQRY];          // sup qry^T        (100x150)
__device__ float g_Hinv  [NBATCH * NWAY * NSUP * NSUP];   // per-class H_c^{-1}
__device__ float g_t     [NBATCH * NWAY * NSUP];          // t_c = Hinv_c r1_c
__device__ float g_z  [NBATCH * NZV];
__device__ float g_s  [NBATCH * NZV];
__device__ float g_lam[NBATCH * NZV];
__device__ float g_gz [NBATCH * NZV];                     // running G z
__device__ float g_nu [NBATCH * NSUP];
__device__ float g_rp [NBATCH * NZV];
__device__ float g_rc [NBATCH * NZV];
__device__ float g_r1 [NBATCH * NZV];
__device__ float g_d  [NBATCH * NZV];
__device__ float g_rp2[NBATCH * NSUP];

// ---------------- gram: kernel (100x100) + compat (100x150) ----------------
// grid (32, 4), block 400. Output columns: 0..99 -> kernel, 100..249 -> compat.
__global__ void __launch_bounds__(400) k_gram(const float* __restrict__ sup,
                                              const float* __restrict__ qry) {
    int b  = blockIdx.x;
    int c0 = blockIdx.y * 64;
    __shared__ __align__(16) float As[32 * 100];  // [kk][row]
    __shared__ __align__(16) float Bs[32 * 64];   // [kk][col]
    int tid = threadIdx.x;
    int tx = tid & 15;        // 16 col groups of 4
    int ty = tid >> 4;        // 25 row groups of 4
    float acc[4][4];
#pragma unroll
    for (int u = 0; u < 4; u++)
#pragma unroll
        for (int v = 0; v < 4; v++) acc[u][v] = 0.f;

    const float* supb = sup + (size_t)b * NSUP * 512;
    const float* qryb = qry + (size_t)b * NQRY * 512;

    for (int kt = 0; kt < 512; kt += 32) {
        __syncthreads();
        for (int e = tid; e < NSUP * 32; e += 400) {
            int r = e >> 5, kk = e & 31;
            As[kk * 100 + r] = supb[r * 512 + kt + kk];
        }
        for (int e = tid; e < 64 * 32; e += 400) {
            int cc = e >> 5, kk = e & 31;
            int col = c0 + cc;
            float v = 0.f;
            if (col < NSUP)      v = supb[col * 512 + kt + kk];
            else if (col < 250)  v = qryb[(col - NSUP) * 512 + kt + kk];
            Bs[kk * 64 + cc] = v;
        }
        __syncthreads();
#pragma unroll
        for (int kk = 0; kk < 32; kk++) {
            float4 a  = *(const float4*)(As + kk * 100 + 4 * ty);
            float4 bb = *(const float4*)(Bs + kk * 64 + 4 * tx);
            acc[0][0] = fmaf(a.x, bb.x, acc[0][0]); acc[0][1] = fmaf(a.x, bb.y, acc[0][1]);
            acc[0][2] = fmaf(a.x, bb.z, acc[0][2]); acc[0][3] = fmaf(a.x, bb.w, acc[0][3]);
            acc[1][0] = fmaf(a.y, bb.x, acc[1][0]); acc[1][1] = fmaf(a.y, bb.y, acc[1][1]);
            acc[1][2] = fmaf(a.y, bb.z, acc[1][2]); acc[1][3] = fmaf(a.y, bb.w, acc[1][3]);
            acc[2][0] = fmaf(a.z, bb.x, acc[2][0]); acc[2][1] = fmaf(a.z, bb.y, acc[2][1]);
            acc[2][2] = fmaf(a.z, bb.z, acc[2][2]); acc[2][3] = fmaf(a.z, bb.w, acc[2][3]);
            acc[3][0] = fmaf(a.w, bb.x, acc[3][0]); acc[3][1] = fmaf(a.w, bb.y, acc[3][1]);
            acc[3][2] = fmaf(a.w, bb.z, acc[3][2]); acc[3][3] = fmaf(a.w, bb.w, acc[3][3]);
        }
    }
#pragma unroll
    for (int u = 0; u < 4; u++) {
        int r = 4 * ty + u;
#pragma unroll
        for (int v = 0; v < 4; v++) {
            int col = c0 + 4 * tx + v;
            if (col < NSUP)
                g_krn[b * NSUP * NSUP + r * NSUP + col] = acc[u][v];
            else if (col < 250)
                g_compat[b * NSUP * NQRY + r * NQRY + (col - NSUP)] = acc[u][v];
        }
    }
}

// ---------------- init: state (0,0,1,1), gz = 0, closed-form residuals ----------------
__global__ void __launch_bounds__(256) k_init(const int* __restrict__ lab) {
    int b = blockIdx.x, tid = threadIdx.x;
    for (int i = tid; i < NZV; i += 256) {
        int gi = b * NZV + i;
        int ss = i / NWAY, c = i - ss * NWAY;
        float y = (lab[b * NSUP + ss] == c) ? 1.f : 0.f;
        g_z[gi] = 0.f; g_s[gi] = 1.f; g_lam[gi] = 1.f; g_gz[gi] = 0.f;
        // s=1, lam=1, z=0, nu=0, mu=1:
        float rd = 1.f - y;                 // Gz - y + lam + nu
        float rp = 1.f - 0.1f * y;          // z + s - C*y
        float rc = 0.9f;                    // lam*s - 0.1*mu
        g_rp[gi] = rp;
        g_rc[gi] = rc;
        g_d [gi] = 1.f;
        g_r1[gi] = -rd + (rc - rp);         // invs = 1
    }
    for (int ss = tid; ss < NSUP; ss += 256) {
        g_nu [b * NSUP + ss] = 0.f;
        g_rp2[b * NSUP + ss] = 0.f;
    }
}

// ---------------- per-class inversion: register-resident Gauss-Jordan ----------------
// grid = 320 (b*10+c), block = 400. thread = (r = tid%100, cg = tid/100).
// Each thread owns row r, 28 columns [28*cg, 28*cg+28) of a 112-wide row:
// cols 0..99 = H (becomes Hinv in place), col 100 = r1 (becomes t), 101..111 = 0 pad.
// Per step only the pivot row/column go through shared (double-buffered, 1 barrier).
__global__ void __launch_bounds__(400) k_invert() {
    int bc = blockIdx.x;
    int b = bc / NWAY, c = bc - b * NWAY;
    int tid = threadIdx.x;
    int r  = tid % NSUP;
    int cg = tid / NSUP;       // 0..3
    int base = 28 * cg;

    float A[28];
    __shared__ __align__(16) float s_piv[2][112];
    __shared__ float s_col[2][NSUP];
    __shared__ float s_inv[2];

    const float* K = g_krn + b * NSUP * NSUP;
    float dval = 1.0f + g_d[b * NZV + r * NWAY + c];
    float r1v  = g_r1[b * NZV + r * NWAY + c];
#pragma unroll
    for (int jj = 0; jj < 28; jj++) {
        int j = base + jj;
        float v = 0.f;
        if (j < NSUP) { v = K[r * NSUP + j]; if (j == r) v += dval; }
        else if (j == NSUP) v = r1v;
        A[jj] = v;
    }
    // write step-0 staging
    {
        int cgk = 0;
        if (r == 0) {
#pragma unroll
            for (int jj = 0; jj < 28; jj += 4)
                *(float4*)&s_piv[0][base + jj] = make_float4(A[jj], A[jj+1], A[jj+2], A[jj+3]);
        }
        if (cg == cgk) {
            float v = A[0]; // idx = 0
            s_col[0][r] = v;
            if (r == 0) s_inv[0] = 1.0f / v;
        }
    }
    __syncthreads();

    for (int k = 0; k < NSUP; k++) {
        int buf = k & 1;
        float invp = s_inv[buf];
        float t = s_col[buf][r] * invp;

        if (r == k) {
            // row k := scaled pivot row; diagonal slot := invp
#pragma unroll
            for (int jj = 0; jj < 28; jj++) {
                float sv = s_piv[buf][base + jj] * invp;
                A[jj] = (base + jj == k) ? invp : sv;
            }
        } else if (cg == (k / 28)) {
            // owner chunk: generic update + column-k fixup (in-place inverse)
#pragma unroll
            for (int jj = 0; jj < 28; jj++) {
                float upd = fmaf(-t, s_piv[buf][base + jj], A[jj]);
                A[jj] = (base + jj == k) ? (-t) : upd;
            }
        } else {
#pragma unroll
            for (int jj = 0; jj < 28; jj++)
                A[jj] = fmaf(-t, s_piv[buf][base + jj], A[jj]);
        }

        // stage step k+1 (other buffer; no barrier needed before writes)
        if (k + 1 < NSUP) {
            int nb = (k + 1) & 1;
            int kn = k + 1;
            if (r == kn) {
#pragma unroll
                for (int jj = 0; jj < 28; jj += 4)
                    *(float4*)&s_piv[nb][base + jj] = make_float4(A[jj], A[jj+1], A[jj+2], A[jj+3]);
            }
            if (cg == (kn / 28)) {
                int idx = kn - base;
                float v = 0.f;
#pragma unroll
                for (int jj = 0; jj < 28; jj++) v = (jj == idx) ? A[jj] : v;
                s_col[nb][r] = v;
                if (r == kn) s_inv[nb] = 1.0f / v;
            }
        }
        __syncthreads();
    }

    // epilogue: Hinv rows + t
    float* Ho = g_Hinv + (size_t)bc * (NSUP * NSUP) + r * NSUP;
#pragma unroll
    for (int jj = 0; jj < 28; jj++) {
        int j = base + jj;
        if (j < NSUP)       Ho[j] = A[jj];
        else if (j == NSUP) g_t[bc * NSUP + r] = A[jj];
    }
}

// ---------------- Schur solve + step + residuals ----------------
// grid = 32, block = 512 (16 warps).
__global__ void __launch_bounds__(512) k_schur(const int* __restrict__ lab) {
    int b = blockIdx.x, tid = threadIdx.x;
    int lane = tid & 31, w = tid >> 5;
    __shared__ float S[NSUP * 101];
    __shared__ float xv[NSUP];          // rhs -> dnu
    __shared__ float nu_sh[NSUP];
    __shared__ float s_dz[NZV];         // dz, later z_new
    __shared__ float red[32];

    const float* Hb = g_Hinv + (size_t)b * NWAY * NSUP * NSUP;

    // Phase A: S = sum_c Hinv_c ; rhs = sum_c t_c + rp2
    for (int e = tid; e < NSUP * NSUP; e += 512) {
        float acc = 0.f;
#pragma unroll
        for (int c = 0; c < NWAY; c++) acc += Hb[c * (NSUP * NSUP) + e];
        int i = e / NSUP, j = e - i * NSUP;
        S[i * 101 + j] = acc;
    }
    for (int ss = tid; ss < NSUP; ss += 512) {
        float acc = g_rp2[b * NSUP + ss];
#pragma unroll
        for (int c = 0; c < NWAY; c++) acc += g_t[(b * NWAY + c) * NSUP + ss];
        xv[ss] = acc;
        nu_sh[ss] = g_nu[b * NSUP + ss];
    }
    __syncthreads();

    // Phase B: Jordan elimination on trailing columns (no row scaling), 1 barrier/step.
    for (int k = 0; k < NSUP; k++) {
        float invp = 1.0f / S[k * 101 + k];
        float rk = xv[k];
        float skj[4];
#pragma unroll
        for (int m = 0; m < 4; m++) {
            int j = k + 1 + lane + 32 * m;
            skj[m] = (j < NSUP) ? S[k * 101 + j] : 0.f;
        }
        for (int i = w; i < NSUP; i += 16) {
            if (i == k) continue;
            float f = S[i * 101 + k] * invp;
#pragma unroll
            for (int m = 0; m < 4; m++) {
                int j = k + 1 + lane + 32 * m;
                if (j < NSUP) S[i * 101 + j] = fmaf(-f, skj[m], S[i * 101 + j]);
            }
            if (lane == 0) xv[i] = fmaf(-f, rk, xv[i]);
        }
        __syncthreads();
    }
    if (tid < NSUP) xv[tid] = xv[tid] / S[tid * 101 + tid];   // dnu
    __syncthreads();

    // Phase D: dz (warp per row, coalesced lanes over columns)
    for (int ri = w; ri < NZV; ri += 16) {
        int ss = ri / NWAY, c = ri - ss * NWAY;
        const float* Hrow = Hb + (size_t)c * (NSUP * NSUP) + ss * NSUP;
        float acc = 0.f;
#pragma unroll
        for (int m = 0; m < 4; m++) {
            int j = lane + 32 * m;
            if (j < NSUP) acc = fmaf(Hrow[j], xv[j], acc);
        }
#pragma unroll
        for (int off = 16; off; off >>= 1) acc += __shfl_xor_sync(0xffffffffu, acc, off);
        if (lane == 0) s_dz[ri] = g_t[(b * NWAY + c) * NSUP + ss] - acc;
    }
    __syncthreads();

    // Phase E: steps, alpha, state update, residuals
    const float FINF = __int_as_float(0x7f800000);
    float dzv[2], dsv[2], dlv[2], sv[2], lv[2], zv[2], gzv[2];
    float amin = FINF;
#pragma unroll
    for (int q = 0; q < 2; q++) {
        int i = tid + q * 512;
        if (i < NZV) {
            int gi = b * NZV + i;
            float dz = s_dz[i];
            float s0 = g_s[gi], l0 = g_lam[gi];
            float ds = -g_rp[gi] - dz;
            float dl = (-g_rc[gi] - l0 * ds) / s0;
            dzv[q] = dz; dsv[q] = ds; dlv[q] = dl; sv[q] = s0; lv[q] = l0;
            if (ds < 0.f) amin = fminf(amin, -s0 / ds);
            if (dl < 0.f) amin = fminf(amin, -l0 / dl);
        }
    }
#pragma unroll
    for (int off = 16; off; off >>= 1) amin = fminf(amin, __shfl_xor_sync(0xffffffffu, amin, off));
    if (lane == 0) red[w] = amin;
    __syncthreads();
    if (w == 0) {
        float v = (lane < 16) ? red[lane] : FINF;
#pragma unroll
        for (int off = 8; off; off >>= 1) v = fminf(v, __shfl_xor_sync(0xffffffffu, v, off));
        if (lane == 0) red[0] = v;
    }
    __syncthreads();
    float alpha = fminf(1.0f, 0.99f * red[0]);
    __syncthreads();

    // state update + Gz tracking + mu accumulation
    float muloc = 0.f;
#pragma unroll
    for (int q = 0; q < 2; q++) {
        int i = tid + q * 512;
        if (i < NZV) {
            int gi = b * NZV + i;
            int ss = i / NWAY;
            float zn = g_z[gi] + alpha * dzv[q]; g_z[gi] = zn; zv[q] = zn;
            float sn = sv[q] + alpha * dsv[q];   g_s[gi] = sn; sv[q] = sn;
            float ln = lv[q] + alpha * dlv[q];   g_lam[gi] = ln; lv[q] = ln;
            // (G dz)_i = r1_i - dnu[ss] - d_i * dz_i   (exact: H dz = r1 - dnu)
            float gdz = g_r1[gi] - xv[ss] - g_d[gi] * dzv[q];
            float gzn = g_gz[gi] + alpha * gdz;  g_gz[gi] = gzn; gzv[q] = gzn;
            muloc += sn * ln;
            s_dz[i] = zn;   // only this thread ever read s_dz[i]; safe reuse as z_new
        }
    }
    if (tid < NSUP) {
        float nn = nu_sh[tid] + alpha * xv[tid];
        nu_sh[tid] = nn;
        g_nu[b * NSUP + tid] = nn;
    }
    // mu reduction (sum)
#pragma unroll
    for (int off = 16; off; off >>= 1) muloc += __shfl_xor_sync(0xffffffffu, muloc, off);
    if (lane == 0) red[w] = muloc;
    __syncthreads();
    if (w == 0) {
        float v = (lane < 16) ? red[lane] : 0.f;
#pragma unroll
        for (int off = 8; off; off >>= 1) v += __shfl_xor_sync(0xffffffffu, v, off);
        if (lane == 0) red[0] = v;
    }
    __syncthreads();
    float mu = red[0] * (1.0f / (float)NZV);

    // rp2 from z_new in smem
    if (tid < NSUP) {
        float acc = 0.f;
#pragma unroll
        for (int c = 0; c < NWAY; c++) acc += s_dz[tid * NWAY + c];
        g_rp2[b * NSUP + tid] = acc;
    }

    // residuals for next iteration (elementwise; no matvec)
#pragma unroll
    for (int q = 0; q < 2; q++) {
        int i = tid + q * 512;
        if (i < NZV) {
            int gi = b * NZV + i;
            int ss = i / NWAY, c = i - ss * NWAY;
            float y = (lab[b * NSUP + ss] == c) ? 1.f : 0.f;
            float rd = gzv[q] - y + lv[q] + nu_sh[ss];
            float rp = zv[q] + sv[q] - 0.1f * y;
            float rc = lv[q] * sv[q] - 0.1f * mu;
            float invs = 1.0f / sv[q];
            g_rp[gi] = rp;
            g_rc[gi] = rc;
            g_d [gi] = lv[q] * invs;
            g_r1[gi] = -rd + (rc - lv[q] * rp) * invs;
        }
    }
}

// ---------------- logits epilogue ----------------
__global__ void __launch_bounds__(256) k_logits(float* __restrict__ out) {
    int b = blockIdx.x, tid = threadIdx.x;
    __shared__ float sh_z[NZV];
    for (int i = tid; i < NZV; i += 256) sh_z[i] = g_z[b * NZV + i];
    __syncthreads();
    const float* cb = &g_compat[b * NSUP * NQRY];
    for (int o = tid; o < NQRY * NWAY; o += 256) {
        int q = o / NWAY, n = o - q * NWAY;
        float acc = 0.f;
        for (int s = 0; s < NSUP; s++)
            acc = fmaf(cb[s * NQRY + q], sh_z[s * NWAY + n], acc);
        out[b * NQRY * NWAY + o] = acc;
    }
}

// ---------------- launcher ----------------
extern "C" void kernel_launch(void* const* d_in, const int* in_sizes, int n_in,
                              void* d_out, int out_size) {
    const float* sup = (const float*)d_in[0];   // (32,10,10,512)
    const int*   lab = (const int*)  d_in[1];   // (32,10,10)
    const float* qry = (const float*)d_in[2];   // (32,10,15,512)
    float* out = (float*)d_out;                 // (32,150,10)

    k_gram<<<dim3(NBATCH, 4), 400>>>(sup, qry);
    k_init<<<NBATCH, 256>>>(lab);
    for (int it = 0; it < 15; ++it) {
        k_invert<<<NBATCH * NWAY, 400>>>();
        k_schur<<<NBATCH, 512>>>(lab);
    }
    k_logits<<<NBATCH, 256>>>(out);
}

// round 9
// speedup vs baseline: 1.7618x; 1.5728x over previous
#include <cuda_runtime.h>
#include <cuda_bf16.h>

#define NBATCH 32
#define NSUP   100
#define NWAY   10
#define NZV    1000
#define NQRY   150

// ---------------- device scratch ----------------
__device__ float g_krn   [NBATCH * NSUP * NSUP];          // sup sup^T (bitwise symmetric)
__device__ float g_compat[NBATCH * NSUP * NQRY];
__device__ float g_Hinv  [NBATCH * NWAY * NSUP * NSUP];   // [bc][j*100+i] (symmetric)
__device__ float g_t     [NBATCH * NWAY * NSUP];
// all NZV-state arrays use i2 = c*100 + ss layout
__device__ float g_z  [NBATCH * NZV];
__device__ float g_s  [NBATCH * NZV];
__device__ float g_lam[NBATCH * NZV];
__device__ float g_gz [NBATCH * NZV];
__device__ float g_rp [NBATCH * NZV];
__device__ float g_rc [NBATCH * NZV];
__device__ float g_r1 [NBATCH * NZV];
__device__ float g_d  [NBATCH * NZV];
__device__ float g_nu [NBATCH * NSUP];
__device__ float g_rp2[NBATCH * NSUP];

// ---------------- gram: kernel (100x100) + compat (100x150) ----------------
__global__ void __launch_bounds__(400) k_gram(const float* __restrict__ sup,
                                              const float* __restrict__ qry) {
    int b  = blockIdx.x;
    int c0 = blockIdx.y * 64;
    __shared__ __align__(16) float As[32 * 100];
    __shared__ __align__(16) float Bs[32 * 64];
    int tid = threadIdx.x;
    int tx = tid & 15;
    int ty = tid >> 4;
    float acc[4][4];
#pragma unroll
    for (int u = 0; u < 4; u++)
#pragma unroll
        for (int v = 0; v < 4; v++) acc[u][v] = 0.f;

    const float* supb = sup + (size_t)b * NSUP * 512;
    const float* qryb = qry + (size_t)b * NQRY * 512;

    for (int kt = 0; kt < 512; kt += 32) {
        __syncthreads();
        for (int e = tid; e < NSUP * 32; e += 400) {
            int r = e >> 5, kk = e & 31;
            As[kk * 100 + r] = supb[r * 512 + kt + kk];
        }
        for (int e = tid; e < 64 * 32; e += 400) {
            int cc = e >> 5, kk = e & 31;
            int col = c0 + cc;
            float v = 0.f;
            if (col < NSUP)      v = supb[col * 512 + kt + kk];
            else if (col < 250)  v = qryb[(col - NSUP) * 512 + kt + kk];
            Bs[kk * 64 + cc] = v;
        }
        __syncthreads();
#pragma unroll
        for (int kk = 0; kk < 32; kk++) {
            float4 a  = *(const float4*)(As + kk * 100 + 4 * ty);
            float4 bb = *(const float4*)(Bs + kk * 64 + 4 * tx);
            acc[0][0] = fmaf(a.x, bb.x, acc[0][0]); acc[0][1] = fmaf(a.x, bb.y, acc[0][1]);
            acc[0][2] = fmaf(a.x, bb.z, acc[0][2]); acc[0][3] = fmaf(a.x, bb.w, acc[0][3]);
            acc[1][0] = fmaf(a.y, bb.x, acc[1][0]); acc[1][1] = fmaf(a.y, bb.y, acc[1][1]);
            acc[1][2] = fmaf(a.y, bb.z, acc[1][2]); acc[1][3] = fmaf(a.y, bb.w, acc[1][3]);
            acc[2][0] = fmaf(a.z, bb.x, acc[2][0]); acc[2][1] = fmaf(a.z, bb.y, acc[2][1]);
            acc[2][2] = fmaf(a.z, bb.z, acc[2][2]); acc[2][3] = fmaf(a.z, bb.w, acc[2][3]);
            acc[3][0] = fmaf(a.w, bb.x, acc[3][0]); acc[3][1] = fmaf(a.w, bb.y, acc[3][1]);
            acc[3][2] = fmaf(a.w, bb.z, acc[3][2]); acc[3][3] = fmaf(a.w, bb.w, acc[3][3]);
        }
    }
#pragma unroll
    for (int u = 0; u < 4; u++) {
        int r = 4 * ty + u;
#pragma unroll
        for (int v = 0; v < 4; v++) {
            int col = c0 + 4 * tx + v;
            if (col < NSUP)
                g_krn[b * NSUP * NSUP + r * NSUP + col] = acc[u][v];
            else if (col < 250)
                g_compat[b * NSUP * NQRY + r * NQRY + (col - NSUP)] = acc[u][v];
        }
    }
}

// ---------------- init (i2 layout) ----------------
__global__ void __launch_bounds__(256) k_init(const int* __restrict__ lab) {
    int b = blockIdx.x, tid = threadIdx.x;
    for (int i = tid; i < NZV; i += 256) {
        int gi = b * NZV + i;
        int ss = i % NSUP, c = i / NSUP;
        float y = (lab[b * NSUP + ss] == c) ? 1.f : 0.f;
        g_z[gi] = 0.f; g_s[gi] = 1.f; g_lam[gi] = 1.f; g_gz[gi] = 0.f;
        float rd = 1.f - y;
        float rp = 1.f - 0.1f * y;
        float rc = 0.9f;
        g_rp[gi] = rp;
        g_rc[gi] = rc;
        g_d [gi] = 1.f;
        g_r1[gi] = -rd + (rc - rp);
    }
    for (int ss = tid; ss < NSUP; ss += 256) {
        g_nu [b * NSUP + ss] = 0.f;
        g_rp2[b * NSUP + ss] = 0.f;
    }
}

// ---------------- symmetric sweep core (register-resident) ----------------
// thread owns row r, cols [base, base+28) of a 112-wide augmented row
// (col 100 = rhs/r1 border, >100 = zero pad). srow = double-buffered pivot row.
__device__ __forceinline__ void sweep100(float A[28], float (*srow)[112],
                                         int r, int base) {
    for (int k = 0; k < NSUP; k++) {
        int buf = k & 1, nb = buf ^ 1;
        const float* row = srow[buf];
        float invp = __fdividef(1.0f, row[k]);   // broadcast LDS + fast rcp
        float sr = row[r];
        const float4* rowv = (const float4*)(row + base);
        if (r == k) {
#pragma unroll
            for (int m = 0; m < 7; m++) {
                float4 p = rowv[m];
                int j = base + 4 * m;
                A[4*m+0] = (j+0 == k) ? invp : p.x * invp;
                A[4*m+1] = (j+1 == k) ? invp : p.y * invp;
                A[4*m+2] = (j+2 == k) ? invp : p.z * invp;
                A[4*m+3] = (j+3 == k) ? invp : p.w * invp;
            }
        } else {
            float t = (r < k) ? -sr * invp : sr * invp;
            if (k >= base && k < base + 28) {
#pragma unroll
                for (int m = 0; m < 7; m++) {
                    float4 p = rowv[m];
                    int j = base + 4 * m;
                    float u0 = fmaf(-t, p.x, A[4*m+0]);
                    float u1 = fmaf(-t, p.y, A[4*m+1]);
                    float u2 = fmaf(-t, p.z, A[4*m+2]);
                    float u3 = fmaf(-t, p.w, A[4*m+3]);
                    A[4*m+0] = (j+0 == k) ? -t : u0;
                    A[4*m+1] = (j+1 == k) ? -t : u1;
                    A[4*m+2] = (j+2 == k) ? -t : u2;
                    A[4*m+3] = (j+3 == k) ? -t : u3;
                }
            } else {
#pragma unroll
                for (int m = 0; m < 7; m++) {
                    float4 p = rowv[m];
                    A[4*m+0] = fmaf(-t, p.x, A[4*m+0]);
                    A[4*m+1] = fmaf(-t, p.y, A[4*m+1]);
                    A[4*m+2] = fmaf(-t, p.z, A[4*m+2]);
                    A[4*m+3] = fmaf(-t, p.w, A[4*m+3]);
                }
            }
        }
        if (r == k + 1) {
#pragma unroll
            for (int m = 0; m < 7; m++)
                ((float4*)(srow[nb] + base))[m] =
                    make_float4(A[4*m], A[4*m+1], A[4*m+2], A[4*m+3]);
        }
        __syncthreads();
    }
}

// ---------------- per-class inversion (grid=320, block=400) ----------------
__global__ void __launch_bounds__(400, 2) k_invert() {
    int bc = blockIdx.x;
    int b = bc / NWAY, c = bc - b * NWAY;
    int tid = threadIdx.x;
    int r = tid % NSUP, cg = tid / NSUP;
    int base = 28 * cg;
    float A[28];
    __shared__ __align__(16) float srow[2][112];

    const float* K = g_krn + (size_t)b * NSUP * NSUP;
    float dval = 1.0f + g_d[b * NZV + c * NSUP + r];
    float r1v  = g_r1[b * NZV + c * NSUP + r];
#pragma unroll
    for (int jj = 0; jj < 28; jj++) {
        int j = base + jj;
        float v = 0.f;
        if (j < NSUP) { v = K[j * NSUP + r]; if (j == r) v += dval; }   // K symmetric
        else if (j == NSUP) v = r1v;
        A[jj] = v;
    }
    if (r == 0) {
#pragma unroll
        for (int m = 0; m < 7; m++)
            ((float4*)(srow[0] + base))[m] =
                make_float4(A[4*m], A[4*m+1], A[4*m+2], A[4*m+3]);
    }
    __syncthreads();

    sweep100(A, srow, r, base);

    // coalesced transposed store (Hinv symmetric -> identical data)
    float* Ho = g_Hinv + (size_t)bc * (NSUP * NSUP);
#pragma unroll
    for (int jj = 0; jj < 28; jj++) {
        int j = base + jj;
        if (j < NSUP) Ho[j * NSUP + r] = A[jj];
    }
    if (cg == 3) g_t[bc * NSUP + r] = A[16];   // col 100 -> t = Hinv r1
}

// ---------------- Schur solve + step + residuals (grid=32, block=512) ----------------
__global__ void __launch_bounds__(512) k_schur(const int* __restrict__ lab) {
    int b = blockIdx.x, tid = threadIdx.x;
    int lane = tid & 31, w = tid >> 5;
    int r = tid % NSUP, cg = tid / NSUP;   // meaningful for tid<400
    int base = 28 * cg;
    float A[28];
    __shared__ __align__(16) float srow[2][112];
    __shared__ float s_dnu[NSUP];
    __shared__ float s_dz[NZV];
    __shared__ float red[16];
    __shared__ float s_res[2];   // [0]=alpha-helper, [1]=mu-helper

    const float* Hb = g_Hinv + (size_t)b * NWAY * NSUP * NSUP;

    if (tid < 400) {
        // S = sum_c Hinv_c (rows via symmetric/coalesced reads); border col = rhs
#pragma unroll
        for (int jj = 0; jj < 28; jj++) {
            int j = base + jj;
            float v = 0.f;
            if (j < NSUP) {
#pragma unroll
                for (int c = 0; c < NWAY; c++)
                    v += Hb[(size_t)c * (NSUP * NSUP) + j * NSUP + r];
            } else if (j == NSUP) {
                v = g_rp2[b * NSUP + r];
#pragma unroll
                for (int c = 0; c < NWAY; c++)
                    v += g_t[(b * NWAY + c) * NSUP + r];
            }
            A[jj] = v;
        }
        if (r == 0) {
#pragma unroll
            for (int m = 0; m < 7; m++)
                ((float4*)(srow[0] + base))[m] =
                    make_float4(A[4*m], A[4*m+1], A[4*m+2], A[4*m+3]);
        }
    }
    __syncthreads();

    // sweep (idle warps just hit the barriers)
    for (int k = 0; k < NSUP; k++) {
        int buf = k & 1, nb = buf ^ 1;
        if (tid < 400) {
            const float* row = srow[buf];
            float invp = __fdividef(1.0f, row[k]);
            float sr = row[r];
            const float4* rowv = (const float4*)(row + base);
            if (r == k) {
#pragma unroll
                for (int m = 0; m < 7; m++) {
                    float4 p = rowv[m];
                    int j = base + 4 * m;
                    A[4*m+0] = (j+0 == k) ? invp : p.x * invp;
                    A[4*m+1] = (j+1 == k) ? invp : p.y * invp;
                    A[4*m+2] = (j+2 == k) ? invp : p.z * invp;
                    A[4*m+3] = (j+3 == k) ? invp : p.w * invp;
                }
            } else {
                float t = (r < k) ? -sr * invp : sr * invp;
                if (k >= base && k < base + 28) {
#pragma unroll
                    for (int m = 0; m < 7; m++) {
                        float4 p = rowv[m];
                        int j = base + 4 * m;
                        float u0 = fmaf(-t, p.x, A[4*m+0]);
                        float u1 = fmaf(-t, p.y, A[4*m+1]);
                        float u2 = fmaf(-t, p.z, A[4*m+2]);
                        float u3 = fmaf(-t, p.w, A[4*m+3]);
                        A[4*m+0] = (j+0 == k) ? -t : u0;
                        A[4*m+1] = (j+1 == k) ? -t : u1;
                        A[4*m+2] = (j+2 == k) ? -t : u2;
                        A[4*m+3] = (j+3 == k) ? -t : u3;
                    }
                } else {
#pragma unroll
                    for (int m = 0; m < 7; m++) {
                        float4 p = rowv[m];
                        A[4*m+0] = fmaf(-t, p.x, A[4*m+0]);
                        A[4*m+1] = fmaf(-t, p.y, A[4*m+1]);
                        A[4*m+2] = fmaf(-t, p.z, A[4*m+2]);
                        A[4*m+3] = fmaf(-t, p.w, A[4*m+3]);
                    }
                }
            }
            if (r == k + 1) {
#pragma unroll
                for (int m = 0; m < 7; m++)
                    ((float4*)(srow[nb] + base))[m] =
                        make_float4(A[4*m], A[4*m+1], A[4*m+2], A[4*m+3]);
            }
        }
        __syncthreads();
    }
    if (tid < 400 && cg == 3) s_dnu[r] = A[16];   // dnu
    __syncthreads();

    // Phase D: dz (warp per i2 row, coalesced over j thanks to symmetric storage)
    for (int ri = w; ri < NZV; ri += 16) {
        int c = ri / NSUP, ss = ri - c * NSUP;
        const float* Hrow = Hb + (size_t)c * (NSUP * NSUP) + ss * NSUP;
        float acc = 0.f;
#pragma unroll
        for (int m = 0; m < 4; m++) {
            int j = lane + 32 * m;
            if (j < NSUP) acc = fmaf(Hrow[j], s_dnu[j], acc);
        }
#pragma unroll
        for (int off = 16; off; off >>= 1) acc += __shfl_xor_sync(0xffffffffu, acc, off);
        if (lane == 0) s_dz[ri] = g_t[(b * NWAY + c) * NSUP + ss] - acc;
    }
    __syncthreads();

    // Phase E: steps, alpha, state update, residuals (i2 layout)
    const float FINF = __int_as_float(0x7f800000);
    float dzv[2], dsv[2], dlv[2], sv[2], lv[2], zv[2], gzv[2];
    float amin = FINF;
#pragma unroll
    for (int q = 0; q < 2; q++) {
        int i = tid + q * 512;
        if (i < NZV) {
            int gi = b * NZV + i;
            float dz = s_dz[i];
            float s0 = g_s[gi], l0 = g_lam[gi];
            float ds = -g_rp[gi] - dz;
            float dl = (-g_rc[gi] - l0 * ds) / s0;
            dzv[q] = dz; dsv[q] = ds; dlv[q] = dl; sv[q] = s0; lv[q] = l0;
            if (ds < 0.f) amin = fminf(amin, -s0 / ds);
            if (dl < 0.f) amin = fminf(amin, -l0 / dl);
        }
    }
#pragma unroll
    for (int off = 16; off; off >>= 1) amin = fminf(amin, __shfl_xor_sync(0xffffffffu, amin, off));
    if (lane == 0) red[w] = amin;
    __syncthreads();
    if (w == 0) {
        float v = (lane < 16) ? red[lane] : FINF;
#pragma unroll
        for (int off = 8; off; off >>= 1) v = fminf(v, __shfl_xor_sync(0xffffffffu, v, off));
        if (lane == 0) s_res[0] = fminf(1.0f, 0.99f * v);
    }
    __syncthreads();
    float alpha = s_res[0];

    float muloc = 0.f;
#pragma unroll
    for (int q = 0; q < 2; q++) {
        int i = tid + q * 512;
        if (i < NZV) {
            int gi = b * NZV + i;
            int ss = i % NSUP;
            float zn = g_z[gi] + alpha * dzv[q]; g_z[gi] = zn; zv[q] = zn;
            float sn = sv[q] + alpha * dsv[q];   g_s[gi] = sn; sv[q] = sn;
            float ln = lv[q] + alpha * dlv[q];   g_lam[gi] = ln; lv[q] = ln;
            float gdz = g_r1[gi] - s_dnu[ss] - g_d[gi] * dzv[q];   // (G dz)_i exactly
            float gzn = g_gz[gi] + alpha * gdz;  g_gz[gi] = gzn; gzv[q] = gzn;
            muloc += sn * ln;
            s_dz[i] = zn;   // reuse as z_new
        }
    }
#pragma unroll
    for (int off = 16; off; off >>= 1) muloc += __shfl_xor_sync(0xffffffffu, muloc, off);
    if (lane == 0) red[w] = muloc;
    __syncthreads();
    if (w == 0) {
        float v = (lane < 16) ? red[lane] : 0.f;
#pragma unroll
        for (int off = 8; off; off >>= 1) v += __shfl_xor_sync(0xffffffffu, v, off);
        if (lane == 0) s_res[1] = v;
    }
    __syncthreads();
    float mu = s_res[1] * (1.0f / (float)NZV);

    // nu update (overwrite s_dnu with nu_new; dnu fully consumed) + rp2
    if (tid < NSUP) {
        float nn = g_nu[b * NSUP + tid] + alpha * s_dnu[tid];
        s_dnu[tid] = nn;
        g_nu[b * NSUP + tid] = nn;
        float acc = 0.f;
#pragma unroll
        for (int c = 0; c < NWAY; c++) acc += s_dz[c * NSUP + tid];
        g_rp2[b * NSUP + tid] = acc;
    }
    __syncthreads();

    // next-iteration residuals (elementwise; no matvec)
#pragma unroll
    for (int q = 0; q < 2; q++) {
        int i = tid + q * 512;
        if (i < NZV) {
            int gi = b * NZV + i;
            int ss = i % NSUP, c = i / NSUP;
            float y = (lab[b * NSUP + ss] == c) ? 1.f : 0.f;
            float rd = gzv[q] - y + lv[q] + s_dnu[ss];
            float rp = zv[q] + sv[q] - 0.1f * y;
            float rc = lv[q] * sv[q] - 0.1f * mu;
            float invs = 1.0f / sv[q];
            g_rp[gi] = rp;
            g_rc[gi] = rc;
            g_d [gi] = lv[q] * invs;
            g_r1[gi] = -rd + (rc - lv[q] * rp) * invs;
        }
    }
}

// ---------------- logits epilogue ----------------
__global__ void __launch_bounds__(256) k_logits(float* __restrict__ out) {
    int b = blockIdx.x, tid = threadIdx.x;
    __shared__ float sh_z[NZV];
    for (int i = tid; i < NZV; i += 256) sh_z[i] = g_z[b * NZV + i];
    __syncthreads();
    const float* cb = &g_compat[b * NSUP * NQRY];
    for (int o = tid; o < NQRY * NWAY; o += 256) {
        int q = o / NWAY, n = o - q * NWAY;
        float acc = 0.f;
        for (int s = 0; s < NSUP; s++)
            acc = fmaf(cb[s * NQRY + q], sh_z[n * NSUP + s], acc);
        out[b * NQRY * NWAY + o] = acc;
    }
}

// ---------------- launcher ----------------
extern "C" void kernel_launch(void* const* d_in, const int* in_sizes, int n_in,
                              void* d_out, int out_size) {
    const float* sup = (const float*)d_in[0];
    const int*   lab = (const int*)  d_in[1];
    const float* qry = (const float*)d_in[2];
    float* out = (float*)d_out;

    k_gram<<<dim3(NBATCH, 4), 400>>>(sup, qry);
    k_init<<<NBATCH, 256>>>(lab);
    for (int it = 0; it < 15; ++it) {
        k_invert<<<NBATCH * NWAY, 400>>>();
        k_schur<<<NBATCH, 512>>>(lab);
    }
    k_logits<<<NBATCH, 256>>>(out);
}